// round 6
// baseline (speedup 1.0000x reference)
#include <cuda_runtime.h>
#include <cstdint>

// Problem constants
#define NX    2000
#define NZ    4
#define TT    16
#define K2    24000       // nr*nx*nz
#define NJ    8000        // nz*nx
#define NXR   4000        // nx * NR_IN
#define KREL  2000

typedef unsigned long long ull;

// f32x2 packed math (Blackwell)
#define FMA2(d, a, b, c) asm("fma.rn.f32x2 %0, %1, %2, %3;" : "=l"(d) : "l"(a), "l"(b), "l"(c))
#define ADD2(d, a, b)    asm("add.rn.f32x2 %0, %1, %2;"     : "=l"(d) : "l"(a), "l"(b))
#define DUP2(d, s)       asm("mov.b64 %0, {%1, %1};"        : "=l"(d) : "r"(__float_as_uint(s)))

#define CP_ASYNC16(dst, src) asm volatile("cp.async.cg.shared.global [%0], [%1], 16;" :: "r"(dst), "l"(src))
#define CP_COMMIT()          asm volatile("cp.async.commit_group;" ::: "memory")
#define CP_WAIT0()           asm volatile("cp.async.wait_group 0;" ::: "memory")

static __device__ __forceinline__ float2 u2f(ull v) {
    float2 r;
    r.x = __uint_as_float((unsigned)(v & 0xffffffffu));
    r.y = __uint_as_float((unsigned)(v >> 32));
    return r;
}

// z_ctx scratch, t-pair-interleaved: g_zp[tp*K2 + k] = (zctx[2tp][k], zctx[2tp+1][k])
__device__ __align__(16) float2 g_zp[8 * K2];

// ---------------------------------------------------------------------------
// Kernel 1 (fused prep): blocks [0,125) do the relation GEMM slices;
// blocks [125,157) do the identity slice. One wave, one launch.
// ---------------------------------------------------------------------------
#define RELCTAS 125
#define IDCTAS  32
__global__ __launch_bounds__(256) void k_prep(const float* __restrict__ A,
                                              const float* __restrict__ factors,
                                              const int* __restrict__ t_idx) {
    __shared__ float4 As4[32 * 24];    // 32 rows x 96 y (12 KB)
    __shared__ float4 Bs4[96 * 16];    // 96 y x 16 t    (24 KB)

    const int tid = threadIdx.x;

    if (blockIdx.x >= RELCTAS) {
        // ---- identity slice: g_zp[tp][k] (k < 8000) = (factors[ti0][k], factors[ti1][k])
        // float4-granular over k pairs: 8 tp x 4000 k4 items
        float4* gz4 = (float4*)g_zp;
        int base = (blockIdx.x - RELCTAS) * 256 + tid;
        for (int it = base; it < 8 * 4000; it += IDCTAS * 256) {
            int tp = it / 4000;
            int k4 = it - tp * 4000;
            int ti0 = __ldg(t_idx + 2 * tp);
            int ti1 = __ldg(t_idx + 2 * tp + 1);
            float2 a = *(const float2*)(factors + ti0 * NJ + 2 * k4);
            float2 b = *(const float2*)(factors + ti1 * NJ + 2 * k4);
            gz4[tp * (K2 / 2) + k4] = make_float4(a.x, b.x, a.y, b.y);
        }
        return;
    }

    // ---- relation GEMM: C[xr][t*4+z] = sum_y A[xr][y] * factors[ti[t]][y][z]
    const int xr0 = blockIdx.x * 32;
    const int a = tid >> 4;        // 0..15 -> rows 2a, 2a+1
    const int t = tid & 15;

    ull acc[2][2];
    acc[0][0] = acc[0][1] = acc[1][0] = acc[1][1] = 0ull;

    const float*      Asf = (const float*)As4;
    const ulonglong2* Bsu = (const ulonglong2*)Bs4;

    for (int yc = 0; yc < 2016; yc += 96) {
        __syncthreads();
        for (int i = tid; i < 768; i += 256) {
            int r  = i / 24;
            int c4 = i - r * 24;
            int y  = yc + c4 * 4;
            float4 v;
            if (y + 3 < KREL) {
                v = *(const float4*)(A + (xr0 + r) * KREL + y);
            } else {
                v.x = (y + 0 < KREL) ? A[(xr0 + r) * KREL + y + 0] : 0.0f;
                v.y = (y + 1 < KREL) ? A[(xr0 + r) * KREL + y + 1] : 0.0f;
                v.z = (y + 2 < KREL) ? A[(xr0 + r) * KREL + y + 2] : 0.0f;
                v.w = (y + 3 < KREL) ? A[(xr0 + r) * KREL + y + 3] : 0.0f;
            }
            As4[r * 24 + c4] = v;
        }
        const float4* f4 = (const float4*)factors;
        for (int i = tid; i < 1536; i += 256) {
            int tt = i / 96;
            int y  = i - tt * 96;
            int yy = yc + y;
            float4 v = make_float4(0.f, 0.f, 0.f, 0.f);
            if (yy < KREL) {
                int ti = __ldg(t_idx + tt);
                v = f4[ti * (NJ / 4) + yy];
            }
            Bs4[y * 16 + tt] = v;
        }
        __syncthreads();

        #pragma unroll 4
        for (int y = 0; y < 96; ++y) {
            float a0 = Asf[(2 * a)     * 96 + y];
            float a1 = Asf[(2 * a + 1) * 96 + y];
            ull a0d, a1d;
            DUP2(a0d, a0);
            DUP2(a1d, a1);
            ulonglong2 bv = Bsu[y * 16 + t];
            FMA2(acc[0][0], a0d, bv.x, acc[0][0]);
            FMA2(acc[0][1], a0d, bv.y, acc[0][1]);
            FMA2(acc[1][0], a1d, bv.x, acc[1][0]);
            FMA2(acc[1][1], a1d, bv.y, acc[1][1]);
        }
    }

    float* gzf = (float*)g_zp;
    const int tp = t >> 1;
    const int h  = t & 1;
    #pragma unroll
    for (int r = 0; r < 2; ++r) {
        int xr  = xr0 + 2 * a + r;
        int x   = xr >> 1;
        int rin = xr & 1;
        int kb  = (rin + 1) * NJ + x * 4;
        float2 v0 = u2f(acc[r][0]);
        float2 v1 = u2f(acc[r][1]);
        gzf[(tp * K2 + kb + 0) * 2 + h] = v0.x;
        gzf[(tp * K2 + kb + 1) * 2 + h] = v0.y;
        gzf[(tp * K2 + kb + 2) * 2 + h] = v1.x;
        gzf[(tp * K2 + kb + 3) * 2 + h] = v1.y;
    }
}

// ---------------------------------------------------------------------------
// Kernel 2: out[t][j] = tanh( sum_k zctx[t][k] * W[j][k] + b[j] )
// M=16, N=8000, K=24000.  DRAM-stream on W (768 MB).
// 143 CTAs x 448 threads (14 warps). Warp owns 4 j rows. Lane l covers
// k = g*64 + 2l (float2 W loads, depth-3 register pipeline -> ~28KB in
// flight per SM, Little's-law ceiling >> LTS cap).
// z chunks (8 tp x 1600 k, 100 KB) double-buffered via cp.async: staging
// fully overlapped with compute.
// ---------------------------------------------------------------------------
#define KC     1600
#define NCH    15        // K2 / KC
#define MAC    25        // macrosteps (64 k) per chunk
#define GTOT   375       // K2 / 64
#define TPB2   448
#define JCTA   56
#define ZROW4  (K2 / 2)  // g_zp float4 per tp-row = 12000
#define ZCH4   (KC / 2)  // float4 per tp per chunk = 800
#define ZSTG   (8 * ZCH4) // 6400 float4 per chunk buffer

__global__ __launch_bounds__(TPB2, 1) void k_biggemm(const float* __restrict__ W,
                                                     const float* __restrict__ b,
                                                     float* __restrict__ out) {
    extern __shared__ float4 zs4[];    // [2][8][800] float4 = 200 KB
    const int tid = threadIdx.x;
    const int w   = tid >> 5;
    const int l   = tid & 31;
    const int jbase = blockIdx.x * JCTA + w * 4;

    const float* Wp[4];
    #pragma unroll
    for (int jj = 0; jj < 4; ++jj) {
        int j = jbase + jj;
        Wp[jj] = W + (long)min(j, NJ - 1) * K2 + 2 * l;   // lane base
    }

    ull acc[4][8];
    #pragma unroll
    for (int jj = 0; jj < 4; ++jj)
        #pragma unroll
        for (int tp = 0; tp < 8; ++tp) acc[jj][tp] = 0ull;

    const uint32_t zs_s = (uint32_t)__cvta_generic_to_shared(zs4);
    const float4* gz4 = (const float4*)g_zp;

    // stage chunk 0 into buffer 0
    for (int i = tid; i < ZSTG; i += TPB2) {
        int tp = i / ZCH4;
        int m  = i - tp * ZCH4;
        CP_ASYNC16(zs_s + (unsigned)i * 16u, gz4 + tp * ZROW4 + m);
    }
    CP_COMMIT();

    // W register pipeline: w0 = macrostep g, w1 = g+1
    float2 w0[4], w1[4];
    #pragma unroll
    for (int jj = 0; jj < 4; ++jj) {
        w0[jj] = *(const float2*)(Wp[jj]);
        w1[jj] = *(const float2*)(Wp[jj] + 64);
    }

    int g = 0;
    for (int c = 0; c < NCH; ++c) {
        CP_WAIT0();
        __syncthreads();
        // prefetch next chunk into the other buffer (overlapped with compute)
        if (c + 1 < NCH) {
            uint32_t dstb = zs_s + (unsigned)(((c + 1) & 1) * ZSTG) * 16u;
            const float4* srcb = gz4 + (c + 1) * ZCH4;
            for (int i = tid; i < ZSTG; i += TPB2) {
                int tp = i / ZCH4;
                int m  = i - tp * ZCH4;
                CP_ASYNC16(dstb + (unsigned)i * 16u, srcb + tp * ZROW4 + m);
            }
            CP_COMMIT();
        }

        const ulonglong2* zbuf = (const ulonglong2*)zs4 + (c & 1) * ZSTG;

        #pragma unroll 1
        for (int m = 0; m < MAC; ++m, ++g) {
            // prefetch macrostep g+2 (distance ~2 macrosteps > DRAM latency)
            const int g2 = g + 2;
            float2 wn[4];
            if (g2 < GTOT) {
                #pragma unroll
                for (int jj = 0; jj < 4; ++jj)
                    wn[jj] = *(const float2*)(Wp[jj] + g2 * 64);
            } else {
                #pragma unroll
                for (int jj = 0; jj < 4; ++jj) wn[jj] = make_float2(0.f, 0.f);
            }

            // broadcast-duplicate current W values once
            ull wx2[4], wy2[4];
            #pragma unroll
            for (int jj = 0; jj < 4; ++jj) {
                DUP2(wx2[jj], w0[jj].x);
                DUP2(wy2[jj], w0[jj].y);
            }

            const ulonglong2* zrow = zbuf + m * 32 + l;
            // tp half 0
            {
                ulonglong2 zz[4];
                #pragma unroll
                for (int tp = 0; tp < 4; ++tp) zz[tp] = zrow[tp * (KC / 2)];
                #pragma unroll
                for (int jj = 0; jj < 4; ++jj)
                    #pragma unroll
                    for (int tp = 0; tp < 4; ++tp) {
                        FMA2(acc[jj][tp], wx2[jj], zz[tp].x, acc[jj][tp]);
                        FMA2(acc[jj][tp], wy2[jj], zz[tp].y, acc[jj][tp]);
                    }
            }
            // tp half 1
            {
                ulonglong2 zz[4];
                #pragma unroll
                for (int tp = 0; tp < 4; ++tp) zz[tp] = zrow[(tp + 4) * (KC / 2)];
                #pragma unroll
                for (int jj = 0; jj < 4; ++jj)
                    #pragma unroll
                    for (int tp = 0; tp < 4; ++tp) {
                        FMA2(acc[jj][tp + 4], wx2[jj], zz[tp].x, acc[jj][tp + 4]);
                        FMA2(acc[jj][tp + 4], wy2[jj], zz[tp].y, acc[jj][tp + 4]);
                    }
            }

            #pragma unroll
            for (int jj = 0; jj < 4; ++jj) { w0[jj] = w1[jj]; w1[jj] = wn[jj]; }
        }
    }

    // butterfly reduce across lanes
    #pragma unroll
    for (int off = 16; off; off >>= 1) {
        #pragma unroll
        for (int jj = 0; jj < 4; ++jj)
            #pragma unroll
            for (int tp = 0; tp < 8; ++tp) {
                ull o = __shfl_xor_sync(0xffffffffu, acc[jj][tp], off);
                ADD2(acc[jj][tp], acc[jj][tp], o);
            }
    }

    // epilogue: lane l < 16 handles t = l
    if (l < 16) {
        const int tp = l >> 1;
        const int h  = l & 1;
        #pragma unroll
        for (int jj = 0; jj < 4; ++jj) {
            int j = jbase + jj;
            if (j < NJ) {
                float2 f = u2f(acc[jj][tp]);
                float s = h ? f.y : f.x;
                out[l * NJ + j] = tanhf(s + __ldg(b + j));
            }
        }
    }
}

// ---------------------------------------------------------------------------
extern "C" void kernel_launch(void* const* d_in, const int* in_sizes, int n_in,
                              void* d_out, int out_size) {
    const float* relations = (const float*)d_in[0];  // (2000, 2, 2000)
    const float* factors   = (const float*)d_in[1];  // (200, 2000, 4)
    const float* W_dyn     = (const float*)d_in[2];  // (8000, 24000)
    const float* b_dyn     = (const float*)d_in[3];  // (8000,)
    const int*   t_idx     = (const int*)d_in[4];    // (16,) int32
    float* out = (float*)d_out;                      // (16, 8000)

    cudaFuncSetAttribute(k_biggemm, cudaFuncAttributeMaxDynamicSharedMemorySize,
                         2 * ZSTG * (int)sizeof(float4));

    // prep: relation GEMM (125 CTAs) + identity slice (32 CTAs), one wave
    k_prep<<<RELCTAS + IDCTAS, 256>>>(relations, factors, t_idx);
    // big fused GEMM + bias + tanh
    k_biggemm<<<(NJ + JCTA - 1) / JCTA, TPB2, 2 * ZSTG * (int)sizeof(float4)>>>(W_dyn, b_dyn, out);
}

// round 9
// speedup vs baseline: 1.2023x; 1.2023x over previous
#include <cuda_runtime.h>
#include <cstdint>

// Problem constants
#define NX    2000
#define NZ    4
#define TT    16
#define K2    24000       // nr*nx*nz
#define NJ    8000        // nz*nx
#define NXR   4000        // nx * NR_IN
#define KREL  2000

typedef unsigned long long ull;

// f32x2 packed math (Blackwell)
#define FMA2(d, a, b, c) asm("fma.rn.f32x2 %0, %1, %2, %3;" : "=l"(d) : "l"(a), "l"(b), "l"(c))
#define ADD2(d, a, b)    asm("add.rn.f32x2 %0, %1, %2;"     : "=l"(d) : "l"(a), "l"(b))
#define DUP2(d, s)       asm("mov.b64 %0, {%1, %1};"        : "=l"(d) : "r"(__float_as_uint(s)))

#define CP_ASYNC16(dst, src) asm volatile("cp.async.cg.shared.global [%0], [%1], 16;" :: "r"(dst), "l"(src))
#define CP_COMMIT()          asm volatile("cp.async.commit_group;" ::: "memory")
#define CP_WAIT0()           asm volatile("cp.async.wait_group 0;" ::: "memory")

static __device__ __forceinline__ float2 u2f(ull v) {
    float2 r;
    r.x = __uint_as_float((unsigned)(v & 0xffffffffu));
    r.y = __uint_as_float((unsigned)(v >> 32));
    return r;
}

// z_ctx scratch, t-pair-interleaved: g_zp[tp*K2 + k] = (zctx[2tp][k], zctx[2tp+1][k])
__device__ __align__(16) float2 g_zp[8 * K2];

// ---------------------------------------------------------------------------
// Kernel 1a: identity slice
// ---------------------------------------------------------------------------
__global__ void k_identity(const float* __restrict__ factors,
                           const int* __restrict__ t_idx) {
    int idx = blockIdx.x * blockDim.x + threadIdx.x;   // [0, 8*8000)
    if (idx >= 8 * NJ) return;
    int tp = idx / NJ;
    int k  = idx - tp * NJ;
    int ti0 = __ldg(t_idx + 2 * tp);
    int ti1 = __ldg(t_idx + 2 * tp + 1);
    float2 v;
    v.x = __ldg(factors + ti0 * NJ + k);
    v.y = __ldg(factors + ti1 * NJ + k);
    g_zp[tp * K2 + k] = v;
}

// ---------------------------------------------------------------------------
// Kernel 1b: relation GEMM (R4-validated version, unchanged)
// ---------------------------------------------------------------------------
__global__ __launch_bounds__(256) void k_relgemm(const float* __restrict__ A,
                                                 const float* __restrict__ factors,
                                                 const int* __restrict__ t_idx) {
    __shared__ float4 As4[32 * 24];
    __shared__ float4 Bs4[96 * 16];

    const int tid = threadIdx.x;
    const int xr0 = blockIdx.x * 32;
    const int a = tid >> 4;
    const int t = tid & 15;

    ull acc[2][2];
    acc[0][0] = acc[0][1] = acc[1][0] = acc[1][1] = 0ull;

    const float*      Asf = (const float*)As4;
    const ulonglong2* Bsu = (const ulonglong2*)Bs4;

    for (int yc = 0; yc < 2016; yc += 96) {
        __syncthreads();
        for (int i = tid; i < 768; i += 256) {
            int r  = i / 24;
            int c4 = i - r * 24;
            int y  = yc + c4 * 4;
            float4 v;
            if (y + 3 < KREL) {
                v = *(const float4*)(A + (xr0 + r) * KREL + y);
            } else {
                v.x = (y + 0 < KREL) ? A[(xr0 + r) * KREL + y + 0] : 0.0f;
                v.y = (y + 1 < KREL) ? A[(xr0 + r) * KREL + y + 1] : 0.0f;
                v.z = (y + 2 < KREL) ? A[(xr0 + r) * KREL + y + 2] : 0.0f;
                v.w = (y + 3 < KREL) ? A[(xr0 + r) * KREL + y + 3] : 0.0f;
            }
            As4[r * 24 + c4] = v;
        }
        const float4* f4 = (const float4*)factors;
        for (int i = tid; i < 1536; i += 256) {
            int tt = i / 96;
            int y  = i - tt * 96;
            int yy = yc + y;
            float4 v = make_float4(0.f, 0.f, 0.f, 0.f);
            if (yy < KREL) {
                int ti = __ldg(t_idx + tt);
                v = f4[ti * (NJ / 4) + yy];
            }
            Bs4[y * 16 + tt] = v;
        }
        __syncthreads();

        #pragma unroll 4
        for (int y = 0; y < 96; ++y) {
            float a0 = Asf[(2 * a)     * 96 + y];
            float a1 = Asf[(2 * a + 1) * 96 + y];
            ull a0d, a1d;
            DUP2(a0d, a0);
            DUP2(a1d, a1);
            ulonglong2 bv = Bsu[y * 16 + t];
            FMA2(acc[0][0], a0d, bv.x, acc[0][0]);
            FMA2(acc[0][1], a0d, bv.y, acc[0][1]);
            FMA2(acc[1][0], a1d, bv.x, acc[1][0]);
            FMA2(acc[1][1], a1d, bv.y, acc[1][1]);
        }
    }

    float* gzf = (float*)g_zp;
    const int tp = t >> 1;
    const int h  = t & 1;
    #pragma unroll
    for (int r = 0; r < 2; ++r) {
        int xr  = xr0 + 2 * a + r;
        int x   = xr >> 1;
        int rin = xr & 1;
        int kb  = (rin + 1) * NJ + x * 4;
        float2 v0 = u2f(acc[r][0]);
        float2 v1 = u2f(acc[r][1]);
        gzf[(tp * K2 + kb + 0) * 2 + h] = v0.x;
        gzf[(tp * K2 + kb + 1) * 2 + h] = v0.y;
        gzf[(tp * K2 + kb + 2) * 2 + h] = v1.x;
        gzf[(tp * K2 + kb + 3) * 2 + h] = v1.y;
    }
}

// ---------------------------------------------------------------------------
// Kernel 2: out[t][j] = tanh( sum_k zctx[t][k] * W[j][k] + b[j] )
// M=16, N=8000, K=24000. W stream (768 MB) must run at DRAM rate.
// 143 CTAs x 448 thr (14 warps, 4 j each). Depth-5 ring W pipeline,
// FULLY UNROLLED 25-macrostep chunk body (25 % 5 == 0 -> constant slot
// indices, no shift movs, ~20 outstanding LDG.64/warp = 71 KB/SM in flight).
// z chunks double-buffered via cp.async (2 x 100 KB).
// ---------------------------------------------------------------------------
#define KC     1600
#define NCH    15        // K2 / KC
#define MAC    25        // 64-k macrosteps per chunk
#define DEPTH  5         // W pipeline depth (divides MAC)
#define GTOT   375       // K2 / 64
#define TPB2   448
#define JCTA   56
#define ZROW4  (K2 / 2)  // g_zp float4 per tp-row = 12000
#define ZCH4   (KC / 2)  // float4 per tp per chunk = 800
#define ZSTG   (8 * ZCH4) // 6400 float4 per chunk buffer

__global__ __launch_bounds__(TPB2, 1) void k_biggemm(const float* __restrict__ W,
                                                     const float* __restrict__ b,
                                                     float* __restrict__ out) {
    extern __shared__ float4 zs4[];    // [2][ZSTG] float4 = 200 KB
    const int tid = threadIdx.x;
    const int w   = tid >> 5;
    const int l   = tid & 31;
    int jbase = blockIdx.x * JCTA + w * 4;
    if (jbase > NJ - 4) jbase = NJ - 4;   // tail CTA recomputes rows; stores identical

    // single W base; jj row offsets (jj*K2 floats) fold into LDG immediates
    const float* Wb = W + (long)jbase * K2 + 2 * l;

    ull acc[4][8];
    #pragma unroll
    for (int jj = 0; jj < 4; ++jj)
        #pragma unroll
        for (int tp = 0; tp < 8; ++tp) acc[jj][tp] = 0ull;

    const uint32_t zs_s = (uint32_t)__cvta_generic_to_shared(zs4);
    const float4* gz4 = (const float4*)g_zp;

    // stage chunk 0 into buffer 0
    for (int i = tid; i < ZSTG; i += TPB2) {
        int tp = i / ZCH4;
        int m  = i - tp * ZCH4;
        CP_ASYNC16(zs_s + (unsigned)i * 16u, gz4 + tp * ZROW4 + m);
    }
    CP_COMMIT();

    // preload W pipeline: slot d holds macrostep g=d
    float2 wp[DEPTH][4];
    #pragma unroll
    for (int d = 0; d < DEPTH; ++d)
        #pragma unroll
        for (int jj = 0; jj < 4; ++jj)
            wp[d][jj] = *(const float2*)(Wb + (long)jj * K2 + d * 64);

    #pragma unroll 1
    for (int c = 0; c < NCH; ++c) {
        CP_WAIT0();
        __syncthreads();
        // prefetch next z chunk into the other buffer (overlapped with compute)
        if (c + 1 < NCH) {
            uint32_t dstb = zs_s + (unsigned)(((c + 1) & 1) * ZSTG) * 16u;
            const float4* srcb = gz4 + (c + 1) * ZCH4;
            for (int i = tid; i < ZSTG; i += TPB2) {
                int tp = i / ZCH4;
                int m  = i - tp * ZCH4;
                CP_ASYNC16(dstb + (unsigned)i * 16u, srcb + tp * ZROW4 + m);
            }
            CP_COMMIT();
        }

        const ulonglong2* zbuf = (const ulonglong2*)zs4 + (c & 1) * ZSTG;

        #pragma unroll
        for (int m = 0; m < MAC; ++m) {
            const int slot = m % DEPTH;          // compile-time constant
            const ulonglong2* zrow = zbuf + m * 32 + l;

            // consume wp[slot]: two tp-halves to bound live z registers
            #pragma unroll
            for (int half = 0; half < 2; ++half) {
                ulonglong2 zz[4];
                #pragma unroll
                for (int tp = 0; tp < 4; ++tp)
                    zz[tp] = zrow[(half * 4 + tp) * (KC / 2)];
                #pragma unroll
                for (int jj = 0; jj < 4; ++jj) {
                    ull wx2, wy2;
                    DUP2(wx2, wp[slot][jj].x);
                    DUP2(wy2, wp[slot][jj].y);
                    #pragma unroll
                    for (int tp = 0; tp < 4; ++tp) {
                        FMA2(acc[jj][half * 4 + tp], wx2, zz[tp].x, acc[jj][half * 4 + tp]);
                        FMA2(acc[jj][half * 4 + tp], wy2, zz[tp].y, acc[jj][half * 4 + tp]);
                    }
                }
            }

            // refill slot with macrostep g+DEPTH (clamped address; value unused past end)
            {
                int g5 = c * MAC + m + DEPTH;
                long off = (long)((g5 < GTOT) ? g5 : 0) * 64;
                #pragma unroll
                for (int jj = 0; jj < 4; ++jj)
                    wp[slot][jj] = *(const float2*)(Wb + (long)jj * K2 + off);
            }
        }
    }

    // butterfly reduce across lanes
    #pragma unroll
    for (int off = 16; off; off >>= 1) {
        #pragma unroll
        for (int jj = 0; jj < 4; ++jj)
            #pragma unroll
            for (int tp = 0; tp < 8; ++tp) {
                ull o = __shfl_xor_sync(0xffffffffu, acc[jj][tp], off);
                ADD2(acc[jj][tp], acc[jj][tp], o);
            }
    }

    // epilogue: lane l < 16 handles t = l (jbase clamped so all j valid)
    if (l < 16) {
        const int tp = l >> 1;
        const int h  = l & 1;
        #pragma unroll
        for (int jj = 0; jj < 4; ++jj) {
            int j = jbase + jj;
            float2 f = u2f(acc[jj][tp]);
            float s = h ? f.y : f.x;
            out[l * NJ + j] = tanhf(s + __ldg(b + j));
        }
    }
}

// ---------------------------------------------------------------------------
extern "C" void kernel_launch(void* const* d_in, const int* in_sizes, int n_in,
                              void* d_out, int out_size) {
    const float* relations = (const float*)d_in[0];  // (2000, 2, 2000)
    const float* factors   = (const float*)d_in[1];  // (200, 2000, 4)
    const float* W_dyn     = (const float*)d_in[2];  // (8000, 24000)
    const float* b_dyn     = (const float*)d_in[3];  // (8000,)
    const int*   t_idx     = (const int*)d_in[4];    // (16,) int32
    float* out = (float*)d_out;                      // (16, 8000)

    cudaFuncSetAttribute(k_biggemm, cudaFuncAttributeMaxDynamicSharedMemorySize,
                         2 * ZSTG * (int)sizeof(float4));

    k_identity<<<(8 * NJ + 255) / 256, 256>>>(factors, t_idx);
    k_relgemm<<<NXR / 32, 256>>>(relations, factors, t_idx);
    k_biggemm<<<(NJ + JCTA - 1) / JCTA, TPB2, 2 * ZSTG * (int)sizeof(float4)>>>(W_dyn, b_dyn, out);
}

// round 10
// speedup vs baseline: 1.2491x; 1.0389x over previous
#include <cuda_runtime.h>
#include <cstdint>

// Problem constants
#define NX    2000
#define NZ    4
#define TT    16
#define K2    24000       // nr*nx*nz
#define NJ    8000        // nz*nx
#define NXR   4000        // nx * NR_IN
#define KREL  2000

typedef unsigned long long ull;

// f32x2 packed math (Blackwell)
#define FMA2(d, a, b, c) asm("fma.rn.f32x2 %0, %1, %2, %3;" : "=l"(d) : "l"(a), "l"(b), "l"(c))
#define ADD2(d, a, b)    asm("add.rn.f32x2 %0, %1, %2;"     : "=l"(d) : "l"(a), "l"(b))
#define DUP2(d, s)       asm("mov.b64 %0, {%1, %1};"        : "=l"(d) : "r"(__float_as_uint(s)))

#define CP_ASYNC16(dst, src) asm volatile("cp.async.cg.shared.global [%0], [%1], 16;" :: "r"(dst), "l"(src))
#define CP_COMMIT()          asm volatile("cp.async.commit_group;" ::: "memory")
#define CP_WAIT0()           asm volatile("cp.async.wait_group 0;" ::: "memory")

static __device__ __forceinline__ float2 u2f(ull v) {
    float2 r;
    r.x = __uint_as_float((unsigned)(v & 0xffffffffu));
    r.y = __uint_as_float((unsigned)(v >> 32));
    return r;
}

// z_ctx scratch, t-pair-interleaved: g_zp[tp*K2 + k] = (zctx[2tp][k], zctx[2tp+1][k])
__device__ __align__(16) float2 g_zp[8 * K2];

// ---------------------------------------------------------------------------
// Kernel 1: prep (identity slice fused into relation GEMM CTAs; 125 CTAs,
// single wave). Identity part: 32000 float4 items == 125*256, one per thread.
// ---------------------------------------------------------------------------
__global__ __launch_bounds__(256) void k_prep(const float* __restrict__ A,
                                              const float* __restrict__ factors,
                                              const int* __restrict__ t_idx) {
    __shared__ float4 As4[32 * 24];    // 32 rows x 96 y (12 KB)
    __shared__ float4 Bs4[96 * 16];    // 96 y x 16 t    (24 KB)

    const int tid = threadIdx.x;

    // ---- identity slice: one float4 per thread (covers k = 2*k4, 2*k4+1)
    {
        float4* gz4 = (float4*)g_zp;
        int it = blockIdx.x * 256 + tid;        // [0, 32000)
        int tp = it / 4000;
        int k4 = it - tp * 4000;
        int ti0 = __ldg(t_idx + 2 * tp);
        int ti1 = __ldg(t_idx + 2 * tp + 1);
        float2 a = *(const float2*)(factors + ti0 * NJ + 2 * k4);
        float2 b = *(const float2*)(factors + ti1 * NJ + 2 * k4);
        gz4[tp * (K2 / 2) + k4] = make_float4(a.x, b.x, a.y, b.y);
    }

    // ---- relation GEMM: C[xr][t*4+z] = sum_y A[xr][y] * factors[ti[t]][y][z]
    const int xr0 = blockIdx.x * 32;
    const int a = tid >> 4;        // 0..15 -> rows 2a, 2a+1
    const int t = tid & 15;

    ull acc[2][2];
    acc[0][0] = acc[0][1] = acc[1][0] = acc[1][1] = 0ull;

    const float*      Asf = (const float*)As4;
    const ulonglong2* Bsu = (const ulonglong2*)Bs4;

    for (int yc = 0; yc < 2016; yc += 96) {
        __syncthreads();
        for (int i = tid; i < 768; i += 256) {
            int r  = i / 24;
            int c4 = i - r * 24;
            int y  = yc + c4 * 4;
            float4 v;
            if (y + 3 < KREL) {
                v = *(const float4*)(A + (xr0 + r) * KREL + y);
            } else {
                v.x = (y + 0 < KREL) ? A[(xr0 + r) * KREL + y + 0] : 0.0f;
                v.y = (y + 1 < KREL) ? A[(xr0 + r) * KREL + y + 1] : 0.0f;
                v.z = (y + 2 < KREL) ? A[(xr0 + r) * KREL + y + 2] : 0.0f;
                v.w = (y + 3 < KREL) ? A[(xr0 + r) * KREL + y + 3] : 0.0f;
            }
            As4[r * 24 + c4] = v;
        }
        const float4* f4 = (const float4*)factors;
        for (int i = tid; i < 1536; i += 256) {
            int tt = i / 96;
            int y  = i - tt * 96;
            int yy = yc + y;
            float4 v = make_float4(0.f, 0.f, 0.f, 0.f);
            if (yy < KREL) {
                int ti = __ldg(t_idx + tt);
                v = f4[ti * (NJ / 4) + yy];
            }
            Bs4[y * 16 + tt] = v;
        }
        __syncthreads();

        #pragma unroll 4
        for (int y = 0; y < 96; ++y) {
            float a0 = Asf[(2 * a)     * 96 + y];
            float a1 = Asf[(2 * a + 1) * 96 + y];
            ull a0d, a1d;
            DUP2(a0d, a0);
            DUP2(a1d, a1);
            ulonglong2 bv = Bsu[y * 16 + t];
            FMA2(acc[0][0], a0d, bv.x, acc[0][0]);
            FMA2(acc[0][1], a0d, bv.y, acc[0][1]);
            FMA2(acc[1][0], a1d, bv.x, acc[1][0]);
            FMA2(acc[1][1], a1d, bv.y, acc[1][1]);
        }
    }

    float* gzf = (float*)g_zp;
    const int tp = t >> 1;
    const int h  = t & 1;
    #pragma unroll
    for (int r = 0; r < 2; ++r) {
        int xr  = xr0 + 2 * a + r;
        int x   = xr >> 1;
        int rin = xr & 1;
        int kb  = (rin + 1) * NJ + x * 4;
        float2 v0 = u2f(acc[r][0]);
        float2 v1 = u2f(acc[r][1]);
        gzf[(tp * K2 + kb + 0) * 2 + h] = v0.x;
        gzf[(tp * K2 + kb + 1) * 2 + h] = v0.y;
        gzf[(tp * K2 + kb + 2) * 2 + h] = v1.x;
        gzf[(tp * K2 + kb + 3) * 2 + h] = v1.y;
    }
}

// ---------------------------------------------------------------------------
// Kernel 2: out[t][j] = tanh( sum_k zctx[t][k] * W[j][k] + b[j] )
// M=16, N=8000, K=24000. W stream (768 MB) must run at DRAM rate.
// 143 CTAs x 448 thr (14 warps, 4 j each). DEPTH-3 ring W pipeline sized to
// FIT the 128-reg budget (acc 64 + ring 24 + transients ~20 + addr ~15).
// MAC=15 divisible by DEPTH=3 -> slot indices compile-time across chunks.
// z chunks (8 tp x 960 k, 60 KB) double-buffered via cp.async.
// ---------------------------------------------------------------------------
#define KC     960
#define NCH    25        // K2 / KC
#define MAC    15        // 64-k macrosteps per chunk
#define DEPTH  3         // W pipeline depth (divides MAC)
#define GTOT   375       // K2 / 64
#define TPB2   448
#define JCTA   56
#define ZROW4  (K2 / 2)  // g_zp float4 per tp-row = 12000
#define ZCH4   (KC / 2)  // float4 per tp per chunk = 480
#define ZSTG   (8 * ZCH4) // 3840 float4 per chunk buffer (61440 B)

__global__ __launch_bounds__(TPB2, 1) void k_biggemm(const float* __restrict__ W,
                                                     const float* __restrict__ b,
                                                     float* __restrict__ out) {
    extern __shared__ float4 zs4[];    // [2][ZSTG] float4 = 120 KB
    const int tid = threadIdx.x;
    const int w   = tid >> 5;
    const int l   = tid & 31;
    int jbase = blockIdx.x * JCTA + w * 4;
    if (jbase > NJ - 4) jbase = NJ - 4;   // tail warps recompute rows; stores identical

    // byte-offset base; jj row offsets (jj*96000 B) fold into LDG immediates
    const char* Wb = (const char*)(W + (long)jbase * K2 + 2 * l);

    ull acc[4][8];
    #pragma unroll
    for (int jj = 0; jj < 4; ++jj)
        #pragma unroll
        for (int tp = 0; tp < 8; ++tp) acc[jj][tp] = 0ull;

    const uint32_t zs_s = (uint32_t)__cvta_generic_to_shared(zs4);
    const float4* gz4 = (const float4*)g_zp;

    // stage chunk 0 into buffer 0 (division-free)
    #pragma unroll
    for (int tp = 0; tp < 8; ++tp) {
        CP_ASYNC16(zs_s + (unsigned)(tp * ZCH4 + tid) * 16u, gz4 + tp * ZROW4 + tid);
        if (tid < ZCH4 - TPB2)
            CP_ASYNC16(zs_s + (unsigned)(tp * ZCH4 + TPB2 + tid) * 16u,
                       gz4 + tp * ZROW4 + TPB2 + tid);
    }
    CP_COMMIT();

    // preload W ring: slot d holds macrostep g=d  (invariant: slot s holds g ≡ s mod 3)
    float2 wp[DEPTH][4];
    #pragma unroll
    for (int d = 0; d < DEPTH; ++d)
        #pragma unroll
        for (int jj = 0; jj < 4; ++jj)
            wp[d][jj] = *(const float2*)(Wb + d * 256 + jj * 96000);

    #pragma unroll 1
    for (int c = 0; c < NCH; ++c) {
        CP_WAIT0();
        __syncthreads();
        // prefetch next z chunk into the other buffer (overlapped with compute)
        if (c + 1 < NCH) {
            uint32_t dstb = zs_s + (unsigned)(((c + 1) & 1) * ZSTG) * 16u;
            const float4* srcb = gz4 + (c + 1) * ZCH4;
            #pragma unroll
            for (int tp = 0; tp < 8; ++tp) {
                CP_ASYNC16(dstb + (unsigned)(tp * ZCH4 + tid) * 16u, srcb + tp * ZROW4 + tid);
                if (tid < ZCH4 - TPB2)
                    CP_ASYNC16(dstb + (unsigned)(tp * ZCH4 + TPB2 + tid) * 16u,
                               srcb + tp * ZROW4 + TPB2 + tid);
            }
            CP_COMMIT();
        }

        const ulonglong2* zbuf = (const ulonglong2*)zs4 + (c & 1) * ZSTG;

        #pragma unroll
        for (int m = 0; m < MAC; ++m) {
            const int slot = m % DEPTH;          // compile-time constant (DEPTH | MAC)
            const ulonglong2* zrow = zbuf + m * 32 + l;

            // consume wp[slot]: two tp-halves bound live z registers to 16
            #pragma unroll
            for (int half = 0; half < 2; ++half) {
                ulonglong2 zz[4];
                #pragma unroll
                for (int tp = 0; tp < 4; ++tp)
                    zz[tp] = zrow[(half * 4 + tp) * (KC / 2)];
                #pragma unroll
                for (int jj = 0; jj < 4; ++jj) {
                    ull wx2, wy2;
                    DUP2(wx2, wp[slot][jj].x);
                    DUP2(wy2, wp[slot][jj].y);
                    #pragma unroll
                    for (int tp = 0; tp < 4; ++tp) {
                        FMA2(acc[jj][half * 4 + tp], wx2, zz[tp].x, acc[jj][half * 4 + tp]);
                        FMA2(acc[jj][half * 4 + tp], wy2, zz[tp].y, acc[jj][half * 4 + tp]);
                    }
                }
            }

            // refill slot with macrostep g+DEPTH (clamped address; value unused past end)
            {
                int g3 = c * MAC + m + DEPTH;
                unsigned woff = (unsigned)((g3 < GTOT) ? g3 : 0) * 256u;
                #pragma unroll
                for (int jj = 0; jj < 4; ++jj)
                    wp[slot][jj] = *(const float2*)(Wb + woff + jj * 96000);
            }
        }
    }

    // butterfly reduce across lanes
    #pragma unroll
    for (int off = 16; off; off >>= 1) {
        #pragma unroll
        for (int jj = 0; jj < 4; ++jj)
            #pragma unroll
            for (int tp = 0; tp < 8; ++tp) {
                ull o = __shfl_xor_sync(0xffffffffu, acc[jj][tp], off);
                ADD2(acc[jj][tp], acc[jj][tp], o);
            }
    }

    // epilogue: lane l < 16 handles t = l (jbase clamped so all j valid)
    if (l < 16) {
        const int tp = l >> 1;
        const int h  = l & 1;
        #pragma unroll
        for (int jj = 0; jj < 4; ++jj) {
            int j = jbase + jj;
            float2 f = u2f(acc[jj][tp]);
            float s = h ? f.y : f.x;
            out[l * NJ + j] = tanhf(s + __ldg(b + j));
        }
    }
}

// ---------------------------------------------------------------------------
extern "C" void kernel_launch(void* const* d_in, const int* in_sizes, int n_in,
                              void* d_out, int out_size) {
    const float* relations = (const float*)d_in[0];  // (2000, 2, 2000)
    const float* factors   = (const float*)d_in[1];  // (200, 2000, 4)
    const float* W_dyn     = (const float*)d_in[2];  // (8000, 24000)
    const float* b_dyn     = (const float*)d_in[3];  // (8000,)
    const int*   t_idx     = (const int*)d_in[4];    // (16,) int32
    float* out = (float*)d_out;                      // (16, 8000)

    cudaFuncSetAttribute(k_biggemm, cudaFuncAttributeMaxDynamicSharedMemorySize,
                         2 * ZSTG * (int)sizeof(float4));

    // prep: identity slice fused into relation-GEMM CTAs (125 CTAs, one wave)
    k_prep<<<NXR / 32, 256>>>(relations, factors, t_idx);
    // big fused GEMM + bias + tanh
    k_biggemm<<<(NJ + JCTA - 1) / JCTA, TPB2, 2 * ZSTG * (int)sizeof(float4)>>>(W_dyn, b_dyn, out);
}